// round 12
// baseline (speedup 1.0000x reference)
#include <cuda_runtime.h>
#include <cstdint>
#include <cfloat>

// Sparsemax over rows of 16384 x 4096 fp32.
// Persistent CTAs; next row prefetched via cp.async (LDGSTS) into a shared
// double buffer. TWO barriers per row:
//   - fused pass: each thread reads its OWN prefetched slice (ordered by its
//     own cp.async.wait_group, no barrier needed), gathers {x > T0} into a
//     small shared buffer with running block sum S and count C.
//   - B1; warp 0 runs Michelot from t1=(S-1)/C over the ~25 candidates.
//     A-POSTERIORI PROOF: if the converged t >= T0, every excluded element
//     (<= T0 <= t) contributes 0 to sum(x-t)+, so t is the EXACT tau* for
//     the full row -- no row max needed. Otherwise (t < T0, C==0, or
//     overflow) warp 0 reruns clean full-row Michelot from shared: exact
//     for arbitrary inputs, vanishingly rare for this distribution.
//   - B2; all threads write max(x - tau, 0) from registers.

#define N_COLS      4096
#define THREADS     256
#define CAND_CAP    1024
#define T0          2.5f
#define CTAS_PER_SM 6
#define NBLOCKS     (152 * CTAS_PER_SM)   // one persistent wave on GB300

__global__ __launch_bounds__(THREADS, CTAS_PER_SM)
void sparsemax_kernel(const float* __restrict__ x, float* __restrict__ out,
                      int rows) {
    __shared__ float buf[2][N_COLS];     // 32 KB double buffer
    __shared__ float cand[CAND_CAP];     // 4 KB
    __shared__ int   sh_cnt[2];          // parity-buffered block state
    __shared__ float sh_sum[2];
    __shared__ float sh_tau;

    const int tid    = threadIdx.x;
    const int lane   = tid & 31;
    const int wid    = tid >> 5;
    const int stride = gridDim.x;

    // ---- prologue: init both state slots, prefetch first row ----
    if (tid == 0) {
        sh_cnt[0] = 0;    sh_cnt[1] = 0;
        sh_sum[0] = 0.0f; sh_sum[1] = 0.0f;
    }
    __syncthreads();   // counters visible before first gather

    int r0 = blockIdx.x;
    if (r0 < rows) {
        const float4* g = reinterpret_cast<const float4*>(x + (size_t)r0 * N_COLS);
        uint32_t s = (uint32_t)__cvta_generic_to_shared(&buf[0][0]);
#pragma unroll
        for (int k = 0; k < 4; k++) {
            uint32_t saddr = s + (uint32_t)(tid + k * THREADS) * 16u;
            asm volatile("cp.async.cg.shared.global [%0], [%1], 16;\n"
                         :: "r"(saddr), "l"(g + tid + k * THREADS));
        }
    }
    asm volatile("cp.async.commit_group;\n" ::: "memory");

    int p = 0;
    for (int r = r0; r < rows; r += stride, p ^= 1) {
        // ---- prefetch next row into buf[p^1] ----
        // WAR vs iter-1 fallback readers of buf[p^1]: separated by B2(i-1).
        const int rn = r + stride;
        if (rn < rows) {
            const float4* g = reinterpret_cast<const float4*>(x + (size_t)rn * N_COLS);
            uint32_t s = (uint32_t)__cvta_generic_to_shared(&buf[p ^ 1][0]);
#pragma unroll
            for (int k = 0; k < 4; k++) {
                uint32_t saddr = s + (uint32_t)(tid + k * THREADS) * 16u;
                asm volatile("cp.async.cg.shared.global [%0], [%1], 16;\n"
                             :: "r"(saddr), "l"(g + tid + k * THREADS));
            }
        }
        asm volatile("cp.async.commit_group;\n" ::: "memory");

        // wait for OWN slice of buf[p] (each thread reads only what it
        // itself copied -> per-thread wait_group is sufficient ordering).
        asm volatile("cp.async.wait_group 1;\n" ::: "memory");

        const float4* b = reinterpret_cast<const float4*>(&buf[p][0]);

        // ---- fused pass: own slice -> registers, gather x > T0, S & C ----
        float4 v[4];
        float s_part = 0.0f;
#pragma unroll
        for (int k = 0; k < 4; k++) {
            v[k] = b[tid + k * THREADS];
            float vals[4] = {v[k].x, v[k].y, v[k].z, v[k].w};
#pragma unroll
            for (int j = 0; j < 4; j++) {
                if (vals[j] > T0) {
                    s_part += vals[j];
                    int q = atomicAdd(&sh_cnt[p], 1);
                    if (q < CAND_CAP) cand[q] = vals[j];
                }
            }
        }
#pragma unroll
        for (int o = 16; o > 0; o >>= 1)
            s_part += __shfl_xor_sync(0xffffffffu, s_part, o);
        if (lane == 0 && s_part != 0.0f) atomicAdd(&sh_sum[p], s_part);
        __syncthreads();                                     // B1
        // (B1 also makes ALL slices of buf[p] visible for the fallback:
        //  every thread passed its own wait_group before B1.)

        // reset slot p^1 for next row: previous readers passed B2(i-1)
        // (before B1 here); next writers come after B2(i) below.
        if (tid == 0) { sh_cnt[p ^ 1] = 0; sh_sum[p ^ 1] = 0.0f; }

        // ---- warp 0: Michelot + a-posteriori validity check ----
        if (wid == 0) {
            const int   C = sh_cnt[p];
            const float S = sh_sum[p];
            float t;
            bool ok = (C >= 1 && C <= CAND_CAP);
            if (ok) {
                t = (S - 1.0f) / (float)C;       // Michelot iterate 1
                int c_prev = C;
                for (;;) {
                    float s = 0.0f;
                    int   c = 0;
                    for (int i = lane; i < C; i += 32) {
                        float z = cand[i];
                        if (z > t) { s += z; c++; }
                    }
#pragma unroll
                    for (int o = 16; o > 0; o >>= 1)
                        s += __shfl_xor_sync(0xffffffffu, s, o);
                    c = __reduce_add_sync(0xffffffffu, c);
                    if (c == c_prev) break;      // restricted solution reached
                    t = (s - 1.0f) / (float)c;   // c >= 1 here (t < max elem)
                    c_prev = c;
                }
                if (!(t >= T0)) ok = false;      // proof condition failed
            }
            if (!ok) {
                // clean full-row Michelot from shared (exact, rare)
                const float* src = &buf[p][0];
                t = -FLT_MAX;
                int c_prev = -1;
                for (;;) {
                    float s = 0.0f;
                    int   c = 0;
                    for (int i = lane; i < N_COLS; i += 32) {
                        float z = src[i];
                        if (z > t) { s += z; c++; }
                    }
#pragma unroll
                    for (int o = 16; o > 0; o >>= 1)
                        s += __shfl_xor_sync(0xffffffffu, s, o);
                    c = __reduce_add_sync(0xffffffffu, c);
                    if (c == c_prev) break;
                    t = (s - 1.0f) / (float)c;   // c >= 1 (max always in)
                    c_prev = c;
                }
            }
            if (lane == 0) sh_tau = t;
        }
        __syncthreads();                                     // B2
        const float tau = sh_tau;

        // ---- output straight from registers, streaming stores ----
        float4* orow = reinterpret_cast<float4*>(out + (size_t)r * N_COLS);
#pragma unroll
        for (int k = 0; k < 4; k++) {
            float4 o;
            o.x = fmaxf(v[k].x - tau, 0.0f);
            o.y = fmaxf(v[k].y - tau, 0.0f);
            o.z = fmaxf(v[k].z - tau, 0.0f);
            o.w = fmaxf(v[k].w - tau, 0.0f);
            __stcs(&orow[tid + k * THREADS], o);
        }
    }
}

extern "C" void kernel_launch(void* const* d_in, const int* in_sizes, int n_in,
                              void* d_out, int out_size) {
    const float* x = (const float*)d_in[0];
    float* out = (float*)d_out;
    const int rows = in_sizes[0] / N_COLS;   // 16384
    sparsemax_kernel<<<NBLOCKS, THREADS>>>(x, out, rows);
}

// round 13
// speedup vs baseline: 1.3792x; 1.3792x over previous
#include <cuda_runtime.h>
#include <cstdint>
#include <cfloat>

// Sparsemax over rows of 16384 x 4096 fp32.
// Persistent CTAs, TRIPLE-buffered rows:
//   buf[(i+1)%3] <- cp.async load of row i+1 (in flight)
//   buf[ i   %3] -> max + candidate gather for row i
//   buf[(i-1)%3] -> STORE pass of row i-1 (overlaps warp0's tau solve!)
// Exact sort-free tau: candidates {x > rowmax-1}; Michelot iterate 1 fused
// into the gather (block S,C -> t1=(S-1)/C); warp 0 runs the tiny residual
// fixed point WHILE the other warps store the previous row, so the solve
// is off the critical path. Full-row fallback on candidate overflow.

#define N_COLS      4096
#define THREADS     256
#define CAND_CAP    1024
#define NBLOCKS     608            // 152 SMs * 4 CTAs (53.3KB smem each)
#define SMEM_BYTES  (3 * N_COLS * 4 + CAND_CAP * 4)

__device__ __forceinline__ unsigned enc_f(float f) {
    unsigned u = __float_as_uint(f);
    return (u & 0x80000000u) ? ~u : (u | 0x80000000u);   // order-preserving
}
__device__ __forceinline__ float dec_f(unsigned e) {
    unsigned u = (e & 0x80000000u) ? (e & 0x7fffffffu) : ~e;
    return __uint_as_float(u);
}

__device__ __forceinline__ void cp_row(float* dst, const float* src, int tid) {
    uint32_t s = (uint32_t)__cvta_generic_to_shared(dst);
    const float4* g = reinterpret_cast<const float4*>(src);
#pragma unroll
    for (int k = 0; k < 4; k++) {
        asm volatile("cp.async.cg.shared.global [%0], [%1], 16;\n"
                     :: "r"(s + (uint32_t)(tid + k * THREADS) * 16u),
                        "l"(g + tid + k * THREADS));
    }
}

__global__ __launch_bounds__(THREADS)
void sparsemax_kernel(const float* __restrict__ x, float* __restrict__ out,
                      int rows) {
    extern __shared__ float smem[];
    float* buf  = smem;                  // 3 * N_COLS floats
    float* cand = smem + 3 * N_COLS;     // CAND_CAP floats

    __shared__ unsigned sh_maxbits;
    __shared__ int      sh_cnt;
    __shared__ float    sh_sum;
    __shared__ float    sh_tau;

    const int tid    = threadIdx.x;
    const int lane   = tid & 31;
    const int wid    = tid >> 5;
    const int stride = gridDim.x;

    if (tid == 0) { sh_maxbits = 0u; sh_cnt = 0; sh_sum = 0.0f; }
    __syncthreads();

    const int r0 = blockIdx.x;
    if (r0 < rows) cp_row(buf, x + (size_t)r0 * N_COLS, tid);
    asm volatile("cp.async.commit_group;\n" ::: "memory");

    float tau_prev = 0.0f;
    int it = 0;
    int r;
    for (r = r0; r < rows; r += stride, it++) {
        float* bcur  = buf + (it % 3) * N_COLS;
        float* bprev = buf + ((it + 2) % 3) * N_COLS;   // row i-1
        float* bnext = buf + ((it + 1) % 3) * N_COLS;

        // ---- load row i+1 (WAR vs row i-2's store-reads: same-thread
        //      program order + B3 of iter i-1) ----
        const int rn = r + stride;
        if (rn < rows) cp_row(bnext, x + (size_t)rn * N_COLS, tid);
        asm volatile("cp.async.commit_group;\n" ::: "memory");
        asm volatile("cp.async.wait_group 1;\n" ::: "memory");   // row i ready

        // ---- max pass on own slice of row i ----
        const float4* b = reinterpret_cast<const float4*>(bcur);
        float4 v[4];
        float m = -FLT_MAX;
#pragma unroll
        for (int k = 0; k < 4; k++) {
            v[k] = b[tid + k * THREADS];
            m = fmaxf(m, fmaxf(fmaxf(v[k].x, v[k].y), fmaxf(v[k].z, v[k].w)));
        }
        unsigned we = __reduce_max_sync(0xffffffffu, enc_f(m));
        if (lane == 0) atomicMax(&sh_maxbits, we);
        __syncthreads();                                     // B1

        const float thresh = dec_f(sh_maxbits) - 1.0f;   // tau* >= thresh

        // ---- gather candidates + fused Michelot iteration 1 (S, C) ----
        float s_part = 0.0f;
#pragma unroll
        for (int k = 0; k < 4; k++) {
            float vals[4] = {v[k].x, v[k].y, v[k].z, v[k].w};
#pragma unroll
            for (int j = 0; j < 4; j++) {
                if (vals[j] > thresh) {
                    s_part += vals[j];
                    int q = atomicAdd(&sh_cnt, 1);
                    if (q < CAND_CAP) cand[q] = vals[j];
                }
            }
        }
#pragma unroll
        for (int o = 16; o > 0; o >>= 1)
            s_part += __shfl_xor_sync(0xffffffffu, s_part, o);
        if (lane == 0 && s_part != 0.0f) atomicAdd(&sh_sum, s_part);
        __syncthreads();                                     // B2

        // ---- warp 0: solve tau_i  ||  other warps: store row i-1 ----
        if (wid == 0) {
            const int   C = sh_cnt;                // exact even on overflow
            const float S = sh_sum;
            __syncwarp();
            if (lane == 0) {                       // reset for next row:
                sh_cnt = 0; sh_sum = 0.0f;         //  readers (warp0) done,
                sh_maxbits = 0u;                   //  writers are post-B3
            }
            const float* src = cand;
            int nn = C;
            if (C > CAND_CAP) { nn = N_COLS; src = bcur; }   // rare, exact
            float t = (S - 1.0f) / (float)C;       // Michelot iterate 1
            int c_prev = C;
            for (;;) {
                float s = 0.0f;
                int   c = 0;
                for (int i = lane; i < nn; i += 32) {
                    float z = src[i];
                    if (z > t) { s += z; c++; }
                }
#pragma unroll
                for (int o = 16; o > 0; o >>= 1)
                    s += __shfl_xor_sync(0xffffffffu, s, o);
                c = __reduce_add_sync(0xffffffffu, c);
                if (c == c_prev) break;        // support stabilized -> exact
                t = (s - 1.0f) / (float)c;     // c >= 1 (rowmax in support)
                c_prev = c;
            }
            if (lane == 0) sh_tau = t;
        }
        // store pass for row i-1 (warp0 joins after its solve)
        if (it > 0) {
            const float4* bp = reinterpret_cast<const float4*>(bprev);
            float4* orow = reinterpret_cast<float4*>(out + (size_t)(r - stride) * N_COLS);
#pragma unroll
            for (int k = 0; k < 4; k++) {
                float4 w = bp[tid + k * THREADS];
                float4 o;
                o.x = fmaxf(w.x - tau_prev, 0.0f);
                o.y = fmaxf(w.y - tau_prev, 0.0f);
                o.z = fmaxf(w.z - tau_prev, 0.0f);
                o.w = fmaxf(w.w - tau_prev, 0.0f);
                __stcs(&orow[tid + k * THREADS], o);
            }
        }
        __syncthreads();                                     // B3
        tau_prev = sh_tau;
    }

    // ---- epilogue: store the final row with its tau ----
    if (r0 < rows) {
        const int rl = r - stride;                       // last processed row
        const float4* bp = reinterpret_cast<const float4*>(buf + ((it + 2) % 3) * N_COLS);
        float4* orow = reinterpret_cast<float4*>(out + (size_t)rl * N_COLS);
#pragma unroll
        for (int k = 0; k < 4; k++) {
            float4 w = bp[tid + k * THREADS];
            float4 o;
            o.x = fmaxf(w.x - tau_prev, 0.0f);
            o.y = fmaxf(w.y - tau_prev, 0.0f);
            o.z = fmaxf(w.z - tau_prev, 0.0f);
            o.w = fmaxf(w.w - tau_prev, 0.0f);
            __stcs(&orow[tid + k * THREADS], o);
        }
    }
}

extern "C" void kernel_launch(void* const* d_in, const int* in_sizes, int n_in,
                              void* d_out, int out_size) {
    const float* x = (const float*)d_in[0];
    float* out = (float*)d_out;
    const int rows = in_sizes[0] / N_COLS;   // 16384
    cudaFuncSetAttribute(sparsemax_kernel,
                         cudaFuncAttributeMaxDynamicSharedMemorySize, SMEM_BYTES);
    sparsemax_kernel<<<NBLOCKS, THREADS, SMEM_BYTES>>>(x, out, rows);
}